// round 12
// baseline (speedup 1.0000x reference)
#include <cuda_runtime.h>
#include <cuda_bf16.h>
#include <math.h>

// Problem constants
#define Nn 100000
#define Ee 1600000
#define Ss 4
#define Dd 128
#define Hh 256
#define Pp 10000

#define SCAN_BLOCKS 98   // ceil(100000/1024)

// fused agg+gemm1 smem layout
#define A_STRIDE 136     // 128 + 8 pad (bf16)
#define B_STRIDE 40      // 32 + 8 pad (bf16)
#define SMEM_FUSED (2 * 128 * A_STRIDE * 2 + 2 * 256 * B_STRIDE * 2)  // 110592 B

// ---------------- scratch (device globals; no allocations) ----------------
__device__ __nv_bfloat16 g_W1h[(size_t)Hh * Dd];      // W1^T split [n][k]
__device__ __nv_bfloat16 g_W1l[(size_t)Hh * Dd];
__device__ __nv_bfloat16 g_H1h[Ss][(size_t)Nn * Hh];  // relu out, bf16 hi/lo
__device__ __nv_bfloat16 g_H1l[Ss][(size_t)Nn * Hh];
__device__ float g_AGG2[Ss][(size_t)Pp * Hh];         // Agg(H1)[post] fp32
__device__ float g_ACC [(size_t)Pp * Hh];             // mean post embedding
// 4-deep CSR
__device__ float g_DINV[Ss][Nn];
__device__ int   g_CNT [Ss][Nn];
__device__ int   g_ROWPTR[Ss][Nn + 1];
__device__ int   g_CURS[Ss][Nn];
__device__ int   g_COL [Ss][Ee];
__device__ int   g_BSUM[Ss][SCAN_BLOCKS];

__device__ __forceinline__ void fma4v(float4& a, const float4 v, const float w) {
    a.x = fmaf(v.x, w, a.x); a.y = fmaf(v.y, w, a.y);
    a.z = fmaf(v.z, w, a.z); a.w = fmaf(v.w, w, a.w);
}

__device__ __forceinline__ void split_store2(__nv_bfloat16* Hd, __nv_bfloat16* Ld,
                                             size_t off, float v0, float v1) {
    union { __nv_bfloat16 b[2]; unsigned u; } hh, ll;
    __nv_bfloat16 h0 = __float2bfloat16_rn(v0);
    __nv_bfloat16 h1 = __float2bfloat16_rn(v1);
    hh.b[0] = h0; hh.b[1] = h1;
    ll.b[0] = __float2bfloat16_rn(v0 - __bfloat162float(h0));
    ll.b[1] = __float2bfloat16_rn(v1 - __bfloat162float(h1));
    *reinterpret_cast<unsigned*>(&Hd[off]) = hh.u;
    *reinterpret_cast<unsigned*>(&Ld[off]) = ll.u;
}

__device__ __forceinline__ float4 load_split4(const __nv_bfloat16* Hd,
                                              const __nv_bfloat16* Ld, size_t off) {
    union { __nv_bfloat16 b[4]; uint2 u; } hh, ll;
    hh.u = *reinterpret_cast<const uint2*>(&Hd[off]);
    ll.u = *reinterpret_cast<const uint2*>(&Ld[off]);
    return make_float4(
        __bfloat162float(hh.b[0]) + __bfloat162float(ll.b[0]),
        __bfloat162float(hh.b[1]) + __bfloat162float(ll.b[1]),
        __bfloat162float(hh.b[2]) + __bfloat162float(ll.b[2]),
        __bfloat162float(hh.b[3]) + __bfloat162float(ll.b[3]));
}

__device__ __forceinline__ void mma_bf16(
    float& d0, float& d1, float& d2, float& d3,
    unsigned a0, unsigned a1, unsigned a2, unsigned a3,
    unsigned b0, unsigned b1)
{
    asm volatile(
        "mma.sync.aligned.m16n8k16.row.col.f32.bf16.bf16.f32 "
        "{%0,%1,%2,%3}, {%4,%5,%6,%7}, {%8,%9}, {%0,%1,%2,%3};"
        : "+f"(d0), "+f"(d1), "+f"(d2), "+f"(d3)
        : "r"(a0), "r"(a1), "r"(a2), "r"(a3), "r"(b0), "r"(b1));
}

// ---------------- one-time W1 split (transposed) ----------------
__global__ void split_w1_kernel(const float* __restrict__ W1) {
    int i = blockIdx.x * blockDim.x + threadIdx.x;
    if (i >= Dd * Hh) return;
    int k = i / Hh, n = i % Hh;
    float v = W1[i];
    __nv_bfloat16 h = __float2bfloat16_rn(v);
    g_W1h[(size_t)n * Dd + k] = h;
    g_W1l[(size_t)n * Dd + k] = __float2bfloat16_rn(v - __bfloat162float(h));
}

// ---------------- CSR build ----------------
__global__ void zero_cnt_kernel(int buf) {
    int i = blockIdx.x * blockDim.x + threadIdx.x;
    if (i < Nn) g_CNT[buf][i] = 0;
}

__global__ void count_kernel(const int* __restrict__ dst, int buf) {
    int e = blockIdx.x * blockDim.x + threadIdx.x;
    if (e < Ee) atomicAdd(&g_CNT[buf][dst[e]], 1);
}

__global__ __launch_bounds__(1024) void scan1_kernel(int buf) {
    __shared__ int sh[1024];
    int i = blockIdx.x * 1024 + threadIdx.x;
    int v = (i < Nn) ? g_CNT[buf][i] : 0;
    sh[threadIdx.x] = v;
    __syncthreads();
    for (int off = 1; off < 1024; off <<= 1) {
        int t = 0;
        if (threadIdx.x >= off) t = sh[threadIdx.x - off];
        __syncthreads();
        sh[threadIdx.x] += t;
        __syncthreads();
    }
    if (i < Nn) g_ROWPTR[buf][i] = sh[threadIdx.x] - v;
    if (threadIdx.x == 1023) g_BSUM[buf][blockIdx.x] = sh[1023];
}

// parallel 128-wide Hillis-Steele over 98 block sums (exclusive)
__global__ __launch_bounds__(128) void scan2_kernel(int buf) {
    __shared__ int sh[128];
    int t = threadIdx.x;
    int v = (t < SCAN_BLOCKS) ? g_BSUM[buf][t] : 0;
    sh[t] = v;
    __syncthreads();
    for (int off = 1; off < 128; off <<= 1) {
        int x = 0;
        if (t >= off) x = sh[t - off];
        __syncthreads();
        sh[t] += x;
        __syncthreads();
    }
    if (t < SCAN_BLOCKS) g_BSUM[buf][t] = sh[t] - v;
}

__global__ void scan3_kernel(int buf) {
    int i = blockIdx.x * blockDim.x + threadIdx.x;
    if (i < Nn) {
        int r = g_ROWPTR[buf][i] + g_BSUM[buf][i >> 10];
        g_ROWPTR[buf][i] = r;
        g_CURS[buf][i]   = r;
        g_DINV[buf][i]   = rsqrtf((float)(g_CNT[buf][i] + 1));
    }
    if (i == 0) g_ROWPTR[buf][Nn] = Ee;
}

__global__ void fill_kernel(const int* __restrict__ src,
                            const int* __restrict__ dst, int buf) {
    int e = blockIdx.x * blockDim.x + threadIdx.x;
    if (e < Ee) {
        int d = dst[e];
        int slot = atomicAdd(&g_CURS[buf][d], 1);
        g_COL[buf][slot] = src[e];
    }
}

// ------- FUSED agg+gemm1: H1 = relu(Agg(X) @ W1 + b1), no AX round-trip ----
// Block: 128 nodes x full 256 cols, 512 threads (16 warps, 4x4 warp grid).
__global__ __launch_bounds__(512) void agg_gemm1_kernel(
    const float* __restrict__ X, const float* __restrict__ b1, int buf)
{
    extern __shared__ char smraw[];
    __nv_bfloat16* Ah = reinterpret_cast<__nv_bfloat16*>(smraw);   // [128][136]
    __nv_bfloat16* Al = Ah + 128 * A_STRIDE;
    __nv_bfloat16* Bh = Al + 128 * A_STRIDE;                        // [256][40]
    __nv_bfloat16* Bl = Bh + 256 * B_STRIDE;

    int tid = threadIdx.x;
    int wid = tid >> 5;        // 0..15
    int lane = tid & 31;
    int rowBase = blockIdx.x * 128;

    const int*   COL  = g_COL[buf];
    const float* DINV = g_DINV[buf];
    const int*   RP   = g_ROWPTR[buf];
    const float4* X4 = reinterpret_cast<const float4*>(X);

    // ---- Phase 1: aggregate 8 nodes per warp, split-store into A smem ----
    for (int k = 0; k < 8; k++) {
        int r = wid * 8 + k;
        int i = rowBase + r;
        float4 a = make_float4(0.f, 0.f, 0.f, 0.f);
        if (i < Nn) {
            int beg = RP[i], end = RP[i + 1];
            float di = DINV[i];
            int e = beg;
            for (; e + 3 < end; e += 4) {
                int   s0 = COL[e],   s1 = COL[e + 1];
                int   s2 = COL[e + 2], s3 = COL[e + 3];
                float w0 = DINV[s0] * di, w1 = DINV[s1] * di;
                float w2 = DINV[s2] * di, w3 = DINV[s3] * di;
                float4 v0 = X4[(size_t)s0 * 32 + lane];
                float4 v1 = X4[(size_t)s1 * 32 + lane];
                float4 v2 = X4[(size_t)s2 * 32 + lane];
                float4 v3 = X4[(size_t)s3 * 32 + lane];
                fma4v(a, v0, w0); fma4v(a, v1, w1);
                fma4v(a, v2, w2); fma4v(a, v3, w3);
            }
            for (; e < end; e++) {
                int s0 = COL[e];
                fma4v(a, X4[(size_t)s0 * 32 + lane], DINV[s0] * di);
            }
            fma4v(a, X4[(size_t)i * 32 + lane], di * di);
        }
        // bf16 hi/lo split into smem (lane covers columns 4*lane..4*lane+3)
        union { __nv_bfloat16 b[4]; uint2 u; } hh, ll;
        float vv[4] = {a.x, a.y, a.z, a.w};
#pragma unroll
        for (int j = 0; j < 4; j++) {
            __nv_bfloat16 h = __float2bfloat16_rn(vv[j]);
            hh.b[j] = h;
            ll.b[j] = __float2bfloat16_rn(vv[j] - __bfloat162float(h));
        }
        *reinterpret_cast<uint2*>(&Ah[r * A_STRIDE + 4 * lane]) = hh.u;
        *reinterpret_cast<uint2*>(&Al[r * A_STRIDE + 4 * lane]) = ll.u;
    }
    __syncthreads();

    // ---- Phase 2: bf16x3 MMA against W1t, K=128 in 4 chunks of 32 ----
    int warp_m = wid >> 2;     // 0..3 -> 32-row tile
    int warp_n = wid & 3;      // 0..3 -> 64-col tile
    int g = lane >> 2;
    int c0 = (lane & 3) * 2;

    float d[2][8][4];
#pragma unroll
    for (int im = 0; im < 2; im++)
#pragma unroll
        for (int jn = 0; jn < 8; jn++)
#pragma unroll
            for (int c = 0; c < 4; c++) d[im][jn][c] = 0.f;

    for (int k0 = 0; k0 < Dd; k0 += 32) {
        // load B chunk: W1t[0..256)[k0..k0+32), hi+lo
#pragma unroll
        for (int l = 0; l < 2; l++) {
            int f = tid + l * 512;         // 0..1023
            int r = f >> 2;                // 0..255
            int kc = (f & 3) * 8;          // 0,8,16,24
            uint4 vb  = *reinterpret_cast<const uint4*>(&g_W1h[(size_t)r * Dd + k0 + kc]);
            uint4 vbl = *reinterpret_cast<const uint4*>(&g_W1l[(size_t)r * Dd + k0 + kc]);
            *reinterpret_cast<uint4*>(&Bh[r * B_STRIDE + kc]) = vb;
            *reinterpret_cast<uint4*>(&Bl[r * B_STRIDE + kc]) = vbl;
        }
        __syncthreads();

#pragma unroll
        for (int kf0 = 0; kf0 < 32; kf0 += 16) {
            int kA = k0 + kf0;
            unsigned ah[2][4], al[2][4];
#pragma unroll
            for (int im = 0; im < 2; im++) {
                int br = warp_m * 32 + im * 16 + g;
                ah[im][0] = *reinterpret_cast<const unsigned*>(&Ah[br * A_STRIDE + kA + c0]);
                ah[im][1] = *reinterpret_cast<const unsigned*>(&Ah[(br + 8) * A_STRIDE + kA + c0]);
                ah[im][2] = *reinterpret_cast<const unsigned*>(&Ah[br * A_STRIDE + kA + c0 + 8]);
                ah[im][3] = *reinterpret_cast<const unsigned*>(&Ah[(br + 8) * A_STRIDE + kA + c0 + 8]);
                al[im][0] = *reinterpret_cast<const unsigned*>(&Al[br * A_STRIDE + kA + c0]);
                al[im][1] = *reinterpret_cast<const unsigned*>(&Al[(br + 8) * A_STRIDE + kA + c0]);
                al[im][2] = *reinterpret_cast<const unsigned*>(&Al[br * A_STRIDE + kA + c0 + 8]);
                al[im][3] = *reinterpret_cast<const unsigned*>(&Al[(br + 8) * A_STRIDE + kA + c0 + 8]);
            }
#pragma unroll
            for (int jn = 0; jn < 8; jn++) {
                int bn = warp_n * 64 + jn * 8 + g;
                unsigned bh0 = *reinterpret_cast<const unsigned*>(&Bh[bn * B_STRIDE + kf0 + c0]);
                unsigned bh1 = *reinterpret_cast<const unsigned*>(&Bh[bn * B_STRIDE + kf0 + c0 + 8]);
                unsigned bl0 = *reinterpret_cast<const unsigned*>(&Bl[bn * B_STRIDE + kf0 + c0]);
                unsigned bl1 = *reinterpret_cast<const unsigned*>(&Bl[bn * B_STRIDE + kf0 + c0 + 8]);
#pragma unroll
                for (int im = 0; im < 2; im++) {
                    mma_bf16(d[im][jn][0], d[im][jn][1], d[im][jn][2], d[im][jn][3],
                             ah[im][0], ah[im][1], ah[im][2], ah[im][3], bh0, bh1);
                    mma_bf16(d[im][jn][0], d[im][jn][1], d[im][jn][2], d[im][jn][3],
                             ah[im][0], ah[im][1], ah[im][2], ah[im][3], bl0, bl1);
                    mma_bf16(d[im][jn][0], d[im][jn][1], d[im][jn][2], d[im][jn][3],
                             al[im][0], al[im][1], al[im][2], al[im][3], bh0, bh1);
                }
            }
        }
        __syncthreads();
    }

    // ---- epilogue: +b1, relu, bf16 hi/lo split store ----
    __nv_bfloat16* Ch = g_H1h[buf];
    __nv_bfloat16* Cl = g_H1l[buf];
#pragma unroll
    for (int im = 0; im < 2; im++) {
        int r0 = rowBase + warp_m * 32 + im * 16 + g;
#pragma unroll
        for (int jn = 0; jn < 8; jn++) {
            int col = warp_n * 64 + jn * 8 + c0;
            float bb0 = __ldg(&b1[col]), bb1 = __ldg(&b1[col + 1]);
            if (r0 < Nn) {
                split_store2(Ch, Cl, (size_t)r0 * Hh + col,
                             fmaxf(d[im][jn][0] + bb0, 0.f),
                             fmaxf(d[im][jn][1] + bb1, 0.f));
            }
            if (r0 + 8 < Nn) {
                split_store2(Ch, Cl, (size_t)(r0 + 8) * Hh + col,
                             fmaxf(d[im][jn][2] + bb0, 0.f),
                             fmaxf(d[im][jn][3] + bb1, 0.f));
            }
        }
    }
}

// ---------------- pullH: AGG2[p] = Agg(H1)[post_idx[p]] --------------------
__global__ __launch_bounds__(256) void pullH_kernel(const int* __restrict__ post_idx,
                                                    int buf) {
    int warp = (blockIdx.x * blockDim.x + threadIdx.x) >> 5;
    int lane = threadIdx.x & 31;
    if (warp >= Pp) return;
    int p = warp;
    int i = post_idx[p];
    int beg = g_ROWPTR[buf][i], end = g_ROWPTR[buf][i + 1];
    const int*   COL  = g_COL[buf];
    const float* DINV = g_DINV[buf];
    const __nv_bfloat16* Hh_t = g_H1h[buf];
    const __nv_bfloat16* Hl_t = g_H1l[buf];

    float di = DINV[i];
    float4 a0 = make_float4(0.f, 0.f, 0.f, 0.f);
    float4 a1 = make_float4(0.f, 0.f, 0.f, 0.f);

    int e = beg;
    for (; e + 1 < end; e += 2) {
        int   s0 = COL[e],   s1 = COL[e + 1];
        float w0 = DINV[s0] * di, w1 = DINV[s1] * di;
        float4 v00 = load_split4(Hh_t, Hl_t, (size_t)s0 * Hh + 4 * lane);
        float4 v01 = load_split4(Hh_t, Hl_t, (size_t)s0 * Hh + 128 + 4 * lane);
        float4 v10 = load_split4(Hh_t, Hl_t, (size_t)s1 * Hh + 4 * lane);
        float4 v11 = load_split4(Hh_t, Hl_t, (size_t)s1 * Hh + 128 + 4 * lane);
        fma4v(a0, v00, w0); fma4v(a1, v01, w0);
        fma4v(a0, v10, w1); fma4v(a1, v11, w1);
    }
    if (e < end) {
        int s0 = COL[e];
        float w0 = DINV[s0] * di;
        fma4v(a0, load_split4(Hh_t, Hl_t, (size_t)s0 * Hh + 4 * lane), w0);
        fma4v(a1, load_split4(Hh_t, Hl_t, (size_t)s0 * Hh + 128 + 4 * lane), w0);
    }

    float d2 = di * di;
    fma4v(a0, load_split4(Hh_t, Hl_t, (size_t)i * Hh + 4 * lane), d2);
    fma4v(a1, load_split4(Hh_t, Hl_t, (size_t)i * Hh + 128 + 4 * lane), d2);

    float4* AG = reinterpret_cast<float4*>(g_AGG2[buf]);
    AG[(size_t)p * 64 + lane]      = a0;
    AG[(size_t)p * 64 + 32 + lane] = a1;
}

// ------- gemm2 (FFMA, ONCE): ACC = (0.25*ΣAGG2)@W2 + b2 + 0.25*ΣH1[post] ---
__global__ __launch_bounds__(256) void gemm2_kernel(
    const float* __restrict__ W2, const float* __restrict__ b2,
    const int* __restrict__ post_idx)
{
    const int BM = 128, BN = 128, BK = 16;
    const int M = Pp, K = Hh, Ncol = Hh;
    __shared__ float As[BK][BM];
    __shared__ float Bs[BK][BN];

    int tid = threadIdx.x;
    int rowBase = blockIdx.x * BM;
    int colBase = blockIdx.y * BN;
    int tr = tid >> 4;
    int tc = tid & 15;

    float acc[8][8];
#pragma unroll
    for (int i = 0; i < 8; i++)
#pragma unroll
        for (int j = 0; j < 8; j++) acc[i][j] = 0.f;

    for (int k0 = 0; k0 < K; k0 += BK) {
#pragma unroll
        for (int l = 0; l < 2; l++) {
            int f = tid + l * 256;
            int r = f >> 2;
            int cc = (f & 3) * 4;
            float4 v = make_float4(0.f, 0.f, 0.f, 0.f);
            int gr = rowBase + r;
            if (gr < M) {
                size_t off = (size_t)gr * K + k0 + cc;
                float4 v0 = *reinterpret_cast<const float4*>(&g_AGG2[0][off]);
                float4 v1 = *reinterpret_cast<const float4*>(&g_AGG2[1][off]);
                float4 v2 = *reinterpret_cast<const float4*>(&g_AGG2[2][off]);
                float4 v3 = *reinterpret_cast<const float4*>(&g_AGG2[3][off]);
                v.x = (v0.x + v1.x + v2.x + v3.x) * 0.25f;
                v.y = (v0.y + v1.y + v2.y + v3.y) * 0.25f;
                v.z = (v0.z + v1.z + v2.z + v3.z) * 0.25f;
                v.w = (v0.w + v1.w + v2.w + v3.w) * 0.25f;
            }
            As[cc + 0][r] = v.x; As[cc + 1][r] = v.y;
            As[cc + 2][r] = v.z; As[cc + 3][r] = v.w;
        }
#pragma unroll
        for (int l = 0; l < 2; l++) {
            int f = tid + l * 256;
            int r = f >> 5;
            int cc = (f & 31) * 4;
            float4 v = *reinterpret_cast<const float4*>(
                &W2[(size_t)(k0 + r) * Ncol + colBase + cc]);
            *reinterpret_cast<float4*>(&Bs[r][cc]) = v;
        }
        __syncthreads();

#pragma unroll
        for (int k = 0; k < BK; k++) {
            float ra[8], rb[8];
#pragma unroll
            for (int i = 0; i < 8; i++) ra[i] = As[k][tr * 8 + i];
#pragma unroll
            for (int j = 0; j < 8; j++) rb[j] = Bs[k][tc * 8 + j];
#pragma unroll
            for (int i = 0; i < 8; i++)
#pragma unroll
                for (int j = 0; j < 8; j++)
                    acc[i][j] = fmaf(ra[i], rb[j], acc[i][j]);
        }
        __syncthreads();
    }

#pragma unroll
    for (int i = 0; i < 8; i++) {
        int gr = rowBase + tr * 8 + i;
        if (gr < M) {
            int node = post_idx[gr];
#pragma unroll
            for (int j = 0; j < 8; j += 4) {
                int col = colBase + tc * 8 + j;
                float4 bb = *reinterpret_cast<const float4*>(&b2[col]);
                size_t hoff = (size_t)node * Hh + col;
                float4 h0 = load_split4(g_H1h[0], g_H1l[0], hoff);
                float4 h1 = load_split4(g_H1h[1], g_H1l[1], hoff);
                float4 h2 = load_split4(g_H1h[2], g_H1l[2], hoff);
                float4 h3 = load_split4(g_H1h[3], g_H1l[3], hoff);
                float4 v;
                v.x = acc[i][j]     + bb.x + (h0.x + h1.x + h2.x + h3.x) * 0.25f;
                v.y = acc[i][j + 1] + bb.y + (h0.y + h1.y + h2.y + h3.y) * 0.25f;
                v.z = acc[i][j + 2] + bb.z + (h0.z + h1.z + h2.z + h3.z) * 0.25f;
                v.w = acc[i][j + 3] + bb.w + (h0.w + h1.w + h2.w + h3.w) * 0.25f;
                *reinterpret_cast<float4*>(&g_ACC[(size_t)gr * Hh + col]) = v;
            }
        }
    }
}

// ---------------- classifier ----------------
__global__ __launch_bounds__(128) void classifier_kernel(
    const float* __restrict__ Wc1, const float* __restrict__ bc1,
    const float* __restrict__ Wc2, const float* __restrict__ bc2,
    float* __restrict__ out)
{
    __shared__ float post[Hh];
    __shared__ float red[128];
    int p = blockIdx.x;
    int t = threadIdx.x;
    post[t]       = g_ACC[(size_t)p * Hh + t];
    post[t + 128] = g_ACC[(size_t)p * Hh + t + 128];
    __syncthreads();

    float acc = bc1[t];
#pragma unroll 8
    for (int j = 0; j < Hh; j++)
        acc = fmaf(post[j], Wc1[(size_t)j * 128 + t], acc);
    acc = fmaxf(acc, 0.f);
    float v = acc * Wc2[t];

    red[t] = v;
    __syncthreads();
    for (int off = 64; off > 0; off >>= 1) {
        if (t < off) red[t] += red[t + off];
        __syncthreads();
    }
    if (t == 0) {
        float lg = red[0] + bc2[0];
        out[p] = 1.f / (1.f + expf(-lg));
    }
}

// ------------- launch: 4 chains on main + 2 worker streams ----------------
static cudaStream_t s_sA = nullptr, s_sB = nullptr;
static cudaEvent_t  s_evW, s_evA, s_evB;

static void build_csr(const int* EI, int s, cudaStream_t st) {
    const int nblk_node = (Nn + 255) / 256;
    const int nblk_edge = Ee / 256;
    const int* src = EI + (size_t)s * 2 * Ee;
    const int* dst = src + Ee;
    zero_cnt_kernel<<<nblk_node, 256, 0, st>>>(s);
    count_kernel<<<nblk_edge, 256, 0, st>>>(dst, s);
    scan1_kernel<<<SCAN_BLOCKS, 1024, 0, st>>>(s);
    scan2_kernel<<<1, 128, 0, st>>>(s);
    scan3_kernel<<<nblk_node, 256, 0, st>>>(s);
    fill_kernel<<<nblk_edge, 256, 0, st>>>(src, dst, s);
}

static void run_chain(const float* X, const int* EI, const float* b1,
                      const int* post_idx, int s, cudaStream_t st) {
    const int nblk_ph = (Pp + 7) / 8;
    const int nblk_fused = (Nn + 127) / 128;   // 782
    build_csr(EI, s, st);
    agg_gemm1_kernel<<<nblk_fused, 512, SMEM_FUSED, st>>>(X, b1, s);
    pullH_kernel<<<nblk_ph, 256, 0, st>>>(post_idx, s);
}

extern "C" void kernel_launch(void* const* d_in, const int* in_sizes, int n_in,
                              void* d_out, int out_size)
{
    const float* X        = (const float*)d_in[0];
    const int*   EI       = (const int*)  d_in[1];
    const int*   post_idx = (const int*)  d_in[2];
    const float* W1       = (const float*)d_in[3];
    const float* b1       = (const float*)d_in[4];
    const float* W2       = (const float*)d_in[5];
    const float* b2       = (const float*)d_in[6];
    const float* Wc1      = (const float*)d_in[7];
    const float* bc1      = (const float*)d_in[8];
    const float* Wc2      = (const float*)d_in[9];
    const float* bc2      = (const float*)d_in[10];
    float* out = (float*)d_out;

    if (!s_sA) {
        cudaStreamCreateWithFlags(&s_sA, cudaStreamNonBlocking);
        cudaStreamCreateWithFlags(&s_sB, cudaStreamNonBlocking);
        cudaEventCreateWithFlags(&s_evW, cudaEventDisableTiming);
        cudaEventCreateWithFlags(&s_evA, cudaEventDisableTiming);
        cudaEventCreateWithFlags(&s_evB, cudaEventDisableTiming);
        cudaFuncSetAttribute(agg_gemm1_kernel,
                             cudaFuncAttributeMaxDynamicSharedMemorySize,
                             SMEM_FUSED);
    }

    // main: one-time W1 split, then fork
    split_w1_kernel<<<(Dd * Hh + 255) / 256, 256>>>(W1);
    cudaEventRecord(s_evW, 0);
    cudaStreamWaitEvent(s_sA, s_evW, 0);
    cudaStreamWaitEvent(s_sB, s_evW, 0);

    // chains 0,2 on A; chains 1,3 on B
    run_chain(X, EI, b1, post_idx, 0, s_sA);
    run_chain(X, EI, b1, post_idx, 2, s_sA);
    cudaEventRecord(s_evA, s_sA);
    run_chain(X, EI, b1, post_idx, 1, s_sB);
    run_chain(X, EI, b1, post_idx, 3, s_sB);
    cudaEventRecord(s_evB, s_sB);

    // join: single gemm2 over the snapshot mean, then classify
    cudaStreamWaitEvent(0, s_evA, 0);
    cudaStreamWaitEvent(0, s_evB, 0);
    dim3 g2_grid((Pp + 127) / 128, Hh / 128);
    gemm2_kernel<<<g2_grid, 256>>>(W2, b2, post_idx);
    classifier_kernel<<<Pp, 128>>>(Wc1, bc1, Wc2, bc2, out);
}

// round 13
// speedup vs baseline: 1.2763x; 1.2763x over previous
#include <cuda_runtime.h>
#include <cuda_bf16.h>
#include <math.h>

// Problem constants
#define Nn 100000
#define Ee 1600000
#define Ss 4
#define Dd 128
#define Hh 256
#define Pp 10000

#define SCAN_BLOCKS 98   // ceil(100000/1024)

// ---------------- scratch (device globals; no allocations) ----------------
__device__ __nv_bfloat16 g_AXh[Ss][(size_t)Nn * Dd];  // Agg(X) bf16 hi/lo
__device__ __nv_bfloat16 g_AXl[Ss][(size_t)Nn * Dd];
__device__ __nv_bfloat16 g_W1h[(size_t)Hh * Dd];      // W1^T split [n][k]
__device__ __nv_bfloat16 g_W1l[(size_t)Hh * Dd];
__device__ __nv_bfloat16 g_H1h[Ss][(size_t)Nn * Hh];  // relu out, bf16 hi/lo
__device__ __nv_bfloat16 g_H1l[Ss][(size_t)Nn * Hh];
__device__ float g_AGG2[Ss][(size_t)Pp * Hh];         // Agg(H1)[post] fp32
__device__ float g_ACC [(size_t)Pp * Hh];             // mean post embedding
// 4-deep CSR
__device__ float g_DINV[Ss][Nn];
__device__ int   g_CNT [Ss][Nn];
__device__ int   g_ROWPTR[Ss][Nn + 1];
__device__ int   g_CURS[Ss][Nn];
__device__ int   g_COL [Ss][Ee];
__device__ int   g_BSUM[Ss][SCAN_BLOCKS];

__device__ __forceinline__ void fma4v(float4& a, const float4 v, const float w) {
    a.x = fmaf(v.x, w, a.x); a.y = fmaf(v.y, w, a.y);
    a.z = fmaf(v.z, w, a.z); a.w = fmaf(v.w, w, a.w);
}

__device__ __forceinline__ void split_store4(__nv_bfloat16* Hd, __nv_bfloat16* Ld,
                                             size_t off, float4 v) {
    union { __nv_bfloat16 b[4]; uint2 u; } hh, ll;
    float vv[4] = {v.x, v.y, v.z, v.w};
#pragma unroll
    for (int j = 0; j < 4; j++) {
        __nv_bfloat16 h = __float2bfloat16_rn(vv[j]);
        hh.b[j] = h;
        ll.b[j] = __float2bfloat16_rn(vv[j] - __bfloat162float(h));
    }
    *reinterpret_cast<uint2*>(&Hd[off]) = hh.u;
    *reinterpret_cast<uint2*>(&Ld[off]) = ll.u;
}

__device__ __forceinline__ void split_store2(__nv_bfloat16* Hd, __nv_bfloat16* Ld,
                                             size_t off, float v0, float v1) {
    union { __nv_bfloat16 b[2]; unsigned u; } hh, ll;
    __nv_bfloat16 h0 = __float2bfloat16_rn(v0);
    __nv_bfloat16 h1 = __float2bfloat16_rn(v1);
    hh.b[0] = h0; hh.b[1] = h1;
    ll.b[0] = __float2bfloat16_rn(v0 - __bfloat162float(h0));
    ll.b[1] = __float2bfloat16_rn(v1 - __bfloat162float(h1));
    *reinterpret_cast<unsigned*>(&Hd[off]) = hh.u;
    *reinterpret_cast<unsigned*>(&Ld[off]) = ll.u;
}

__device__ __forceinline__ float4 load_split4(const __nv_bfloat16* Hd,
                                              const __nv_bfloat16* Ld, size_t off) {
    union { __nv_bfloat16 b[4]; uint2 u; } hh, ll;
    hh.u = *reinterpret_cast<const uint2*>(&Hd[off]);
    ll.u = *reinterpret_cast<const uint2*>(&Ld[off]);
    return make_float4(
        __bfloat162float(hh.b[0]) + __bfloat162float(ll.b[0]),
        __bfloat162float(hh.b[1]) + __bfloat162float(ll.b[1]),
        __bfloat162float(hh.b[2]) + __bfloat162float(ll.b[2]),
        __bfloat162float(hh.b[3]) + __bfloat162float(ll.b[3]));
}

// ---------------- one-time W1 split (transposed) ----------------
__global__ void split_w1_kernel(const float* __restrict__ W1) {
    int i = blockIdx.x * blockDim.x + threadIdx.x;
    if (i >= Dd * Hh) return;
    int k = i / Hh, n = i % Hh;
    float v = W1[i];
    __nv_bfloat16 h = __float2bfloat16_rn(v);
    g_W1h[(size_t)n * Dd + k] = h;
    g_W1l[(size_t)n * Dd + k] = __float2bfloat16_rn(v - __bfloat162float(h));
}

// ---------------- CSR build ----------------
__global__ void zero_all_kernel() {   // zero all 4 CNT buffers at once
    int i = blockIdx.x * blockDim.x + threadIdx.x;
    if (i < Ss * Nn) ((int*)g_CNT)[i] = 0;
}

// 4 edges per thread via int4
__global__ void count_kernel(const int* __restrict__ dst, int buf) {
    int e4 = blockIdx.x * blockDim.x + threadIdx.x;
    if (e4 < Ee / 4) {
        int4 d = reinterpret_cast<const int4*>(dst)[e4];
        atomicAdd(&g_CNT[buf][d.x], 1);
        atomicAdd(&g_CNT[buf][d.y], 1);
        atomicAdd(&g_CNT[buf][d.z], 1);
        atomicAdd(&g_CNT[buf][d.w], 1);
    }
}

__global__ __launch_bounds__(1024) void scan1_kernel(int buf) {
    __shared__ int sh[1024];
    int i = blockIdx.x * 1024 + threadIdx.x;
    int v = (i < Nn) ? g_CNT[buf][i] : 0;
    sh[threadIdx.x] = v;
    __syncthreads();
    for (int off = 1; off < 1024; off <<= 1) {
        int t = 0;
        if (threadIdx.x >= off) t = sh[threadIdx.x - off];
        __syncthreads();
        sh[threadIdx.x] += t;
        __syncthreads();
    }
    if (i < Nn) g_ROWPTR[buf][i] = sh[threadIdx.x] - v;
    if (threadIdx.x == 1023) g_BSUM[buf][blockIdx.x] = sh[1023];
}

// parallel 128-wide Hillis-Steele over 98 block sums (exclusive)
__global__ __launch_bounds__(128) void scan2_kernel(int buf) {
    __shared__ int sh[128];
    int t = threadIdx.x;
    int v = (t < SCAN_BLOCKS) ? g_BSUM[buf][t] : 0;
    sh[t] = v;
    __syncthreads();
    for (int off = 1; off < 128; off <<= 1) {
        int x = 0;
        if (t >= off) x = sh[t - off];
        __syncthreads();
        sh[t] += x;
        __syncthreads();
    }
    if (t < SCAN_BLOCKS) g_BSUM[buf][t] = sh[t] - v;
}

__global__ void scan3_kernel(int buf) {
    int i = blockIdx.x * blockDim.x + threadIdx.x;
    if (i < Nn) {
        int r = g_ROWPTR[buf][i] + g_BSUM[buf][i >> 10];
        g_ROWPTR[buf][i] = r;
        g_CURS[buf][i]   = r;
        g_DINV[buf][i]   = rsqrtf((float)(g_CNT[buf][i] + 1));
    }
    if (i == 0) g_ROWPTR[buf][Nn] = Ee;
}

// 4 edges per thread via int4
__global__ void fill_kernel(const int* __restrict__ src,
                            const int* __restrict__ dst, int buf) {
    int e4 = blockIdx.x * blockDim.x + threadIdx.x;
    if (e4 < Ee / 4) {
        int4 s = reinterpret_cast<const int4*>(src)[e4];
        int4 d = reinterpret_cast<const int4*>(dst)[e4];
        int slot;
        slot = atomicAdd(&g_CURS[buf][d.x], 1); g_COL[buf][slot] = s.x;
        slot = atomicAdd(&g_CURS[buf][d.y], 1); g_COL[buf][slot] = s.y;
        slot = atomicAdd(&g_CURS[buf][d.z], 1); g_COL[buf][slot] = s.z;
        slot = atomicAdd(&g_CURS[buf][d.w], 1); g_COL[buf][slot] = s.w;
    }
}

// ---------------- pullX: AX[i] = sum_{j->i} X[j]*dinv_j*dinv_i + X[i]*d2 ---
__global__ __launch_bounds__(256) void pullX_kernel(const float* __restrict__ X,
                                                    int buf) {
    int warp = (blockIdx.x * blockDim.x + threadIdx.x) >> 5;
    int lane = threadIdx.x & 31;
    if (warp >= Nn) return;
    int i = warp;
    int beg = g_ROWPTR[buf][i], end = g_ROWPTR[buf][i + 1];
    const int*   COL  = g_COL[buf];
    const float* DINV = g_DINV[buf];
    const float4* X4 = reinterpret_cast<const float4*>(X);

    float di = DINV[i];
    float4 a = make_float4(0.f, 0.f, 0.f, 0.f);

    int e = beg;
    for (; e + 3 < end; e += 4) {
        int   s0 = COL[e],   s1 = COL[e + 1], s2 = COL[e + 2], s3 = COL[e + 3];
        float w0 = DINV[s0] * di, w1 = DINV[s1] * di;
        float w2 = DINV[s2] * di, w3 = DINV[s3] * di;
        float4 v0 = X4[(size_t)s0 * 32 + lane];
        float4 v1 = X4[(size_t)s1 * 32 + lane];
        float4 v2 = X4[(size_t)s2 * 32 + lane];
        float4 v3 = X4[(size_t)s3 * 32 + lane];
        fma4v(a, v0, w0); fma4v(a, v1, w1); fma4v(a, v2, w2); fma4v(a, v3, w3);
    }
    for (; e < end; e++) {
        int s0 = COL[e];
        fma4v(a, X4[(size_t)s0 * 32 + lane], DINV[s0] * di);
    }

    fma4v(a, X4[(size_t)i * 32 + lane], di * di);

    split_store4(g_AXh[buf], g_AXl[buf], (size_t)i * Dd + 4 * lane, a);
}

// ------------- gemm1 (tc, bf16x3): H1 = relu(AX @ W1 + b1), bf16-split out -
#define BMg 128
#define BNg 128
#define BKg 32
#define APAD 40

__device__ __forceinline__ void mma_bf16(
    float& d0, float& d1, float& d2, float& d3,
    unsigned a0, unsigned a1, unsigned a2, unsigned a3,
    unsigned b0, unsigned b1)
{
    asm volatile(
        "mma.sync.aligned.m16n8k16.row.col.f32.bf16.bf16.f32 "
        "{%0,%1,%2,%3}, {%4,%5,%6,%7}, {%8,%9}, {%0,%1,%2,%3};"
        : "+f"(d0), "+f"(d1), "+f"(d2), "+f"(d3)
        : "r"(a0), "r"(a1), "r"(a2), "r"(a3), "r"(b0), "r"(b1));
}

__global__ __launch_bounds__(256) void gemm1_kernel(const float* __restrict__ b1,
                                                    int buf)
{
    const int K = Dd;   // 128
    const int M = Nn;
    __shared__ __nv_bfloat16 Ah[BMg][APAD];
    __shared__ __nv_bfloat16 Al[BMg][APAD];
    __shared__ __nv_bfloat16 Bh[BNg][APAD];
    __shared__ __nv_bfloat16 Bl[BNg][APAD];

    const __nv_bfloat16* Ah_t = g_AXh[buf];
    const __nv_bfloat16* Al_t = g_AXl[buf];
    __nv_bfloat16* Ch = g_H1h[buf];
    __nv_bfloat16* Cl = g_H1l[buf];

    int tid = threadIdx.x;
    int wid = tid >> 5;
    int lane = tid & 31;
    int warp_m = wid >> 1;
    int warp_n = wid & 1;
    int g = lane >> 2;
    int c0 = (lane & 3) * 2;

    int rowBase = blockIdx.x * BMg;
    int colBase = blockIdx.y * BNg;

    float d[2][8][4];
#pragma unroll
    for (int im = 0; im < 2; im++)
#pragma unroll
        for (int jn = 0; jn < 8; jn++)
#pragma unroll
            for (int c = 0; c < 4; c++) d[im][jn][c] = 0.f;

    const uint4 z4 = make_uint4(0, 0, 0, 0);

    for (int k0 = 0; k0 < K; k0 += BKg) {
#pragma unroll
        for (int l = 0; l < 2; l++) {
            int f = tid + l * 256;
            int r = f >> 2;
            int kc = (f & 3) * 8;
            int gr = rowBase + r;
            uint4 va = z4, vl = z4;
            if (gr < M) {
                va = *reinterpret_cast<const uint4*>(&Ah_t[(size_t)gr * K + k0 + kc]);
                vl = *reinterpret_cast<const uint4*>(&Al_t[(size_t)gr * K + k0 + kc]);
            }
            *reinterpret_cast<uint4*>(&Ah[r][kc]) = va;
            *reinterpret_cast<uint4*>(&Al[r][kc]) = vl;
            int bn = colBase + r;
            uint4 vb  = *reinterpret_cast<const uint4*>(&g_W1h[(size_t)bn * K + k0 + kc]);
            uint4 vbl = *reinterpret_cast<const uint4*>(&g_W1l[(size_t)bn * K + k0 + kc]);
            *reinterpret_cast<uint4*>(&Bh[r][kc]) = vb;
            *reinterpret_cast<uint4*>(&Bl[r][kc]) = vbl;
        }
        __syncthreads();

#pragma unroll
        for (int kf = 0; kf < BKg; kf += 16) {
            unsigned ah[2][4], al[2][4];
#pragma unroll
            for (int im = 0; im < 2; im++) {
                int br = warp_m * 32 + im * 16 + g;
                ah[im][0] = *reinterpret_cast<const unsigned*>(&Ah[br][kf + c0]);
                ah[im][1] = *reinterpret_cast<const unsigned*>(&Ah[br + 8][kf + c0]);
                ah[im][2] = *reinterpret_cast<const unsigned*>(&Ah[br][kf + c0 + 8]);
                ah[im][3] = *reinterpret_cast<const unsigned*>(&Ah[br + 8][kf + c0 + 8]);
                al[im][0] = *reinterpret_cast<const unsigned*>(&Al[br][kf + c0]);
                al[im][1] = *reinterpret_cast<const unsigned*>(&Al[br + 8][kf + c0]);
                al[im][2] = *reinterpret_cast<const unsigned*>(&Al[br][kf + c0 + 8]);
                al[im][3] = *reinterpret_cast<const unsigned*>(&Al[br + 8][kf + c0 + 8]);
            }
#pragma unroll
            for (int jn = 0; jn < 8; jn++) {
                int bn = warp_n * 64 + jn * 8 + g;
                unsigned bh0 = *reinterpret_cast<const unsigned*>(&Bh[bn][kf + c0]);
                unsigned bh1 = *reinterpret_cast<const unsigned*>(&Bh[bn][kf + c0 + 8]);
                unsigned bl0 = *reinterpret_cast<const unsigned*>(&Bl[bn][kf + c0]);
                unsigned bl1 = *reinterpret_cast<const unsigned*>(&Bl[bn][kf + c0 + 8]);
#pragma unroll
                for (int im = 0; im < 2; im++) {
                    mma_bf16(d[im][jn][0], d[im][jn][1], d[im][jn][2], d[im][jn][3],
                             ah[im][0], ah[im][1], ah[im][2], ah[im][3], bh0, bh1);
                    mma_bf16(d[im][jn][0], d[im][jn][1], d[im][jn][2], d[im][jn][3],
                             ah[im][0], ah[im][1], ah[im][2], ah[im][3], bl0, bl1);
                    mma_bf16(d[im][jn][0], d[im][jn][1], d[im][jn][2], d[im][jn][3],
                             al[im][0], al[im][1], al[im][2], al[im][3], bh0, bh1);
                }
            }
        }
        __syncthreads();
    }

    // epilogue: +b1, relu, bf16 hi/lo split store
#pragma unroll
    for (int im = 0; im < 2; im++) {
        int r0 = rowBase + warp_m * 32 + im * 16 + g;
#pragma unroll
        for (int jn = 0; jn < 8; jn++) {
            int col = colBase + warp_n * 64 + jn * 8 + c0;
            float bb0 = __ldg(&b1[col]), bb1 = __ldg(&b1[col + 1]);
            if (r0 < M) {
                split_store2(Ch, Cl, (size_t)r0 * Hh + col,
                             fmaxf(d[im][jn][0] + bb0, 0.f),
                             fmaxf(d[im][jn][1] + bb1, 0.f));
            }
            if (r0 + 8 < M) {
                split_store2(Ch, Cl, (size_t)(r0 + 8) * Hh + col,
                             fmaxf(d[im][jn][2] + bb0, 0.f),
                             fmaxf(d[im][jn][3] + bb1, 0.f));
            }
        }
    }
}

// ---------------- pullH: AGG2[p] = Agg(H1)[post_idx[p]] --------------------
__global__ __launch_bounds__(256) void pullH_kernel(const int* __restrict__ post_idx,
                                                    int buf) {
    int warp = (blockIdx.x * blockDim.x + threadIdx.x) >> 5;
    int lane = threadIdx.x & 31;
    if (warp >= Pp) return;
    int p = warp;
    int i = post_idx[p];
    int beg = g_ROWPTR[buf][i], end = g_ROWPTR[buf][i + 1];
    const int*   COL  = g_COL[buf];
    const float* DINV = g_DINV[buf];
    const __nv_bfloat16* Hh_t = g_H1h[buf];
    const __nv_bfloat16* Hl_t = g_H1l[buf];

    float di = DINV[i];
    float4 a0 = make_float4(0.f, 0.f, 0.f, 0.f);
    float4 a1 = make_float4(0.f, 0.f, 0.f, 0.f);

    int e = beg;
    for (; e + 1 < end; e += 2) {
        int   s0 = COL[e],   s1 = COL[e + 1];
        float w0 = DINV[s0] * di, w1 = DINV[s1] * di;
        float4 v00 = load_split4(Hh_t, Hl_t, (size_t)s0 * Hh + 4 * lane);
        float4 v01 = load_split4(Hh_t, Hl_t, (size_t)s0 * Hh + 128 + 4 * lane);
        float4 v10 = load_split4(Hh_t, Hl_t, (size_t)s1 * Hh + 4 * lane);
        float4 v11 = load_split4(Hh_t, Hl_t, (size_t)s1 * Hh + 128 + 4 * lane);
        fma4v(a0, v00, w0); fma4v(a1, v01, w0);
        fma4v(a0, v10, w1); fma4v(a1, v11, w1);
    }
    if (e < end) {
        int s0 = COL[e];
        float w0 = DINV[s0] * di;
        fma4v(a0, load_split4(Hh_t, Hl_t, (size_t)s0 * Hh + 4 * lane), w0);
        fma4v(a1, load_split4(Hh_t, Hl_t, (size_t)s0 * Hh + 128 + 4 * lane), w0);
    }

    float d2 = di * di;
    fma4v(a0, load_split4(Hh_t, Hl_t, (size_t)i * Hh + 4 * lane), d2);
    fma4v(a1, load_split4(Hh_t, Hl_t, (size_t)i * Hh + 128 + 4 * lane), d2);

    float4* AG = reinterpret_cast<float4*>(g_AGG2[buf]);
    AG[(size_t)p * 64 + lane]      = a0;
    AG[(size_t)p * 64 + 32 + lane] = a1;
}

// ------- gemm2 (FFMA, ONCE): ACC = (0.25*ΣAGG2)@W2 + b2 + 0.25*ΣH1[post] ---
__global__ __launch_bounds__(256) void gemm2_kernel(
    const float* __restrict__ W2, const float* __restrict__ b2,
    const int* __restrict__ post_idx)
{
    const int BM = 128, BN = 128, BK = 16;
    const int M = Pp, K = Hh, Ncol = Hh;
    __shared__ float As[BK][BM];
    __shared__ float Bs[BK][BN];

    int tid = threadIdx.x;
    int rowBase = blockIdx.x * BM;
    int colBase = blockIdx.y * BN;
    int tr = tid >> 4;
    int tc = tid & 15;

    float acc[8][8];
#pragma unroll
    for (int i = 0; i < 8; i++)
#pragma unroll
        for (int j = 0; j < 8; j++) acc[i][j] = 0.f;

    for (int k0 = 0; k0 < K; k0 += BK) {
#pragma unroll
        for (int l = 0; l < 2; l++) {
            int f = tid + l * 256;
            int r = f >> 2;
            int cc = (f & 3) * 4;
            float4 v = make_float4(0.f, 0.f, 0.f, 0.f);
            int gr = rowBase + r;
            if (gr < M) {
                size_t off = (size_t)gr * K + k0 + cc;
                float4 v0 = *reinterpret_cast<const float4*>(&g_AGG2[0][off]);
                float4 v1 = *reinterpret_cast<const float4*>(&g_AGG2[1][off]);
                float4 v2 = *reinterpret_cast<const float4*>(&g_AGG2[2][off]);
                float4 v3 = *reinterpret_cast<const float4*>(&g_AGG2[3][off]);
                v.x = (v0.x + v1.x + v2.x + v3.x) * 0.25f;
                v.y = (v0.y + v1.y + v2.y + v3.y) * 0.25f;
                v.z = (v0.z + v1.z + v2.z + v3.z) * 0.25f;
                v.w = (v0.w + v1.w + v2.w + v3.w) * 0.25f;
            }
            As[cc + 0][r] = v.x; As[cc + 1][r] = v.y;
            As[cc + 2][r] = v.z; As[cc + 3][r] = v.w;
        }
#pragma unroll
        for (int l = 0; l < 2; l++) {
            int f = tid + l * 256;
            int r = f >> 5;
            int cc = (f & 31) * 4;
            float4 v = *reinterpret_cast<const float4*>(
                &W2[(size_t)(k0 + r) * Ncol + colBase + cc]);
            *reinterpret_cast<float4*>(&Bs[r][cc]) = v;
        }
        __syncthreads();

#pragma unroll
        for (int k = 0; k < BK; k++) {
            float ra[8], rb[8];
#pragma unroll
            for (int i = 0; i < 8; i++) ra[i] = As[k][tr * 8 + i];
#pragma unroll
            for (int j = 0; j < 8; j++) rb[j] = Bs[k][tc * 8 + j];
#pragma unroll
            for (int i = 0; i < 8; i++)
#pragma unroll
                for (int j = 0; j < 8; j++)
                    acc[i][j] = fmaf(ra[i], rb[j], acc[i][j]);
        }
        __syncthreads();
    }

#pragma unroll
    for (int i = 0; i < 8; i++) {
        int gr = rowBase + tr * 8 + i;
        if (gr < M) {
            int node = post_idx[gr];
#pragma unroll
            for (int j = 0; j < 8; j += 4) {
                int col = colBase + tc * 8 + j;
                float4 bb = *reinterpret_cast<const float4*>(&b2[col]);
                size_t hoff = (size_t)node * Hh + col;
                float4 h0 = load_split4(g_H1h[0], g_H1l[0], hoff);
                float4 h1 = load_split4(g_H1h[1], g_H1l[1], hoff);
                float4 h2 = load_split4(g_H1h[2], g_H1l[2], hoff);
                float4 h3 = load_split4(g_H1h[3], g_H1l[3], hoff);
                float4 v;
                v.x = acc[i][j]     + bb.x + (h0.x + h1.x + h2.x + h3.x) * 0.25f;
                v.y = acc[i][j + 1] + bb.y + (h0.y + h1.y + h2.y + h3.y) * 0.25f;
                v.z = acc[i][j + 2] + bb.z + (h0.z + h1.z + h2.z + h3.z) * 0.25f;
                v.w = acc[i][j + 3] + bb.w + (h0.w + h1.w + h2.w + h3.w) * 0.25f;
                *reinterpret_cast<float4*>(&g_ACC[(size_t)gr * Hh + col]) = v;
            }
        }
    }
}

// ---------------- classifier ----------------
__global__ __launch_bounds__(128) void classifier_kernel(
    const float* __restrict__ Wc1, const float* __restrict__ bc1,
    const float* __restrict__ Wc2, const float* __restrict__ bc2,
    float* __restrict__ out)
{
    __shared__ float post[Hh];
    __shared__ float red[128];
    int p = blockIdx.x;
    int t = threadIdx.x;
    post[t]       = g_ACC[(size_t)p * Hh + t];
    post[t + 128] = g_ACC[(size_t)p * Hh + t + 128];
    __syncthreads();

    float acc = bc1[t];
#pragma unroll 8
    for (int j = 0; j < Hh; j++)
        acc = fmaf(post[j], Wc1[(size_t)j * 128 + t], acc);
    acc = fmaxf(acc, 0.f);
    float v = acc * Wc2[t];

    red[t] = v;
    __syncthreads();
    for (int off = 64; off > 0; off >>= 1) {
        if (t < off) red[t] += red[t + off];
        __syncthreads();
    }
    if (t == 0) {
        float lg = red[0] + bc2[0];
        out[p] = 1.f / (1.f + expf(-lg));
    }
}

// ------------- launch: 4 chains on main + 2 worker streams ----------------
static cudaStream_t s_sA = nullptr, s_sB = nullptr;
static cudaEvent_t  s_evW, s_evA, s_evB;

static void build_csr(const int* EI, int s, cudaStream_t st) {
    const int nblk_node = (Nn + 255) / 256;
    const int nblk_edge4 = (Ee / 4 + 255) / 256;   // 1563
    const int* src = EI + (size_t)s * 2 * Ee;
    const int* dst = src + Ee;
    count_kernel<<<nblk_edge4, 256, 0, st>>>(dst, s);
    scan1_kernel<<<SCAN_BLOCKS, 1024, 0, st>>>(s);
    scan2_kernel<<<1, 128, 0, st>>>(s);
    scan3_kernel<<<nblk_node, 256, 0, st>>>(s);
    fill_kernel<<<nblk_edge4, 256, 0, st>>>(src, dst, s);
}

static void run_chain(const float* X, const int* EI, const float* b1,
                      const int* post_idx, int s, cudaStream_t st) {
    const int nblk_px = (Nn + 7) / 8;
    const int nblk_ph = (Pp + 7) / 8;
    dim3 g1_grid((Nn + BMg - 1) / BMg, Hh / BNg);
    build_csr(EI, s, st);
    pullX_kernel<<<nblk_px, 256, 0, st>>>(X, s);
    gemm1_kernel<<<g1_grid, 256, 0, st>>>(b1, s);
    pullH_kernel<<<nblk_ph, 256, 0, st>>>(post_idx, s);
}

extern "C" void kernel_launch(void* const* d_in, const int* in_sizes, int n_in,
                              void* d_out, int out_size)
{
    const float* X        = (const float*)d_in[0];
    const int*   EI       = (const int*)  d_in[1];
    const int*   post_idx = (const int*)  d_in[2];
    const float* W1       = (const float*)d_in[3];
    const float* b1       = (const float*)d_in[4];
    const float* W2       = (const float*)d_in[5];
    const float* b2       = (const float*)d_in[6];
    const float* Wc1      = (const float*)d_in[7];
    const float* bc1      = (const float*)d_in[8];
    const float* Wc2      = (const float*)d_in[9];
    const float* bc2      = (const float*)d_in[10];
    float* out = (float*)d_out;

    if (!s_sA) {
        cudaStreamCreateWithFlags(&s_sA, cudaStreamNonBlocking);
        cudaStreamCreateWithFlags(&s_sB, cudaStreamNonBlocking);
        cudaEventCreateWithFlags(&s_evW, cudaEventDisableTiming);
        cudaEventCreateWithFlags(&s_evA, cudaEventDisableTiming);
        cudaEventCreateWithFlags(&s_evB, cudaEventDisableTiming);
    }

    // main: zero all CNT buffers + one-time W1 split, then fork
    zero_all_kernel<<<(Ss * Nn + 255) / 256, 256>>>();
    split_w1_kernel<<<(Dd * Hh + 255) / 256, 256>>>(W1);
    cudaEventRecord(s_evW, 0);
    cudaStreamWaitEvent(s_sA, s_evW, 0);
    cudaStreamWaitEvent(s_sB, s_evW, 0);

    // chains 0,2 on A; chains 1,3 on B
    run_chain(X, EI, b1, post_idx, 0, s_sA);
    run_chain(X, EI, b1, post_idx, 2, s_sA);
    cudaEventRecord(s_evA, s_sA);
    run_chain(X, EI, b1, post_idx, 1, s_sB);
    run_chain(X, EI, b1, post_idx, 3, s_sB);
    cudaEventRecord(s_evB, s_sB);

    // join: single gemm2 over the snapshot mean, then classify
    cudaStreamWaitEvent(0, s_evA, 0);
    cudaStreamWaitEvent(0, s_evB, 0);
    dim3 g2_grid((Pp + 127) / 128, Hh / 128);
    gemm2_kernel<<<g2_grid, 256>>>(W2, b2, post_idx);
    classifier_kernel<<<Pp, 128>>>(Wc1, bc1, Wc2, bc2, out);
}

// round 14
// speedup vs baseline: 1.3152x; 1.0304x over previous
#include <cuda_runtime.h>
#include <cuda_bf16.h>
#include <math.h>

// Problem constants
#define Nn 100000
#define Ee 1600000
#define Ss 4
#define Dd 128
#define Hh 256
#define Pp 10000

#define SCAN_BLOCKS 98   // ceil(100000/1024)

// ---------------- scratch (device globals; no allocations) ----------------
__device__ __nv_bfloat16 g_AXh[Ss][(size_t)Nn * Dd];  // Agg(X) bf16 hi/lo
__device__ __nv_bfloat16 g_AXl[Ss][(size_t)Nn * Dd];
__device__ __nv_bfloat16 g_W1h[(size_t)Hh * Dd];      // W1^T split [n][k]
__device__ __nv_bfloat16 g_W1l[(size_t)Hh * Dd];
__device__ __nv_bfloat16 g_H1h[Ss][(size_t)Nn * Hh];  // relu out, bf16 hi/lo
__device__ __nv_bfloat16 g_H1l[Ss][(size_t)Nn * Hh];
__device__ float g_AGG2[Ss][(size_t)Pp * Hh];         // Agg(H1)[post] fp32
__device__ float g_ACC [(size_t)Pp * Hh];             // mean post embedding
// 4-deep CSR
__device__ float g_DINV[Ss][Nn];
__device__ int   g_CNT [Ss][Nn];
__device__ int   g_ROWPTR[Ss][Nn + 1];
__device__ int   g_CURS[Ss][Nn];
__device__ int   g_COL [Ss][Ee];
__device__ int   g_BSUM[Ss][SCAN_BLOCKS];

__device__ __forceinline__ void fma4v(float4& a, const float4 v, const float w) {
    a.x = fmaf(v.x, w, a.x); a.y = fmaf(v.y, w, a.y);
    a.z = fmaf(v.z, w, a.z); a.w = fmaf(v.w, w, a.w);
}

__device__ __forceinline__ void split_store4(__nv_bfloat16* Hd, __nv_bfloat16* Ld,
                                             size_t off, float4 v) {
    union { __nv_bfloat16 b[4]; uint2 u; } hh, ll;
    float vv[4] = {v.x, v.y, v.z, v.w};
#pragma unroll
    for (int j = 0; j < 4; j++) {
        __nv_bfloat16 h = __float2bfloat16_rn(vv[j]);
        hh.b[j] = h;
        ll.b[j] = __float2bfloat16_rn(vv[j] - __bfloat162float(h));
    }
    *reinterpret_cast<uint2*>(&Hd[off]) = hh.u;
    *reinterpret_cast<uint2*>(&Ld[off]) = ll.u;
}

__device__ __forceinline__ void split_store2(__nv_bfloat16* Hd, __nv_bfloat16* Ld,
                                             size_t off, float v0, float v1) {
    union { __nv_bfloat16 b[2]; unsigned u; } hh, ll;
    __nv_bfloat16 h0 = __float2bfloat16_rn(v0);
    __nv_bfloat16 h1 = __float2bfloat16_rn(v1);
    hh.b[0] = h0; hh.b[1] = h1;
    ll.b[0] = __float2bfloat16_rn(v0 - __bfloat162float(h0));
    ll.b[1] = __float2bfloat16_rn(v1 - __bfloat162float(h1));
    *reinterpret_cast<unsigned*>(&Hd[off]) = hh.u;
    *reinterpret_cast<unsigned*>(&Ld[off]) = ll.u;
}

__device__ __forceinline__ float4 load_split4(const __nv_bfloat16* Hd,
                                              const __nv_bfloat16* Ld, size_t off) {
    union { __nv_bfloat16 b[4]; uint2 u; } hh, ll;
    hh.u = *reinterpret_cast<const uint2*>(&Hd[off]);
    ll.u = *reinterpret_cast<const uint2*>(&Ld[off]);
    return make_float4(
        __bfloat162float(hh.b[0]) + __bfloat162float(ll.b[0]),
        __bfloat162float(hh.b[1]) + __bfloat162float(ll.b[1]),
        __bfloat162float(hh.b[2]) + __bfloat162float(ll.b[2]),
        __bfloat162float(hh.b[3]) + __bfloat162float(ll.b[3]));
}

// ---------------- one-time W1 split (transposed) ----------------
__global__ void split_w1_kernel(const float* __restrict__ W1) {
    int i = blockIdx.x * blockDim.x + threadIdx.x;
    if (i >= Dd * Hh) return;
    int k = i / Hh, n = i % Hh;
    float v = W1[i];
    __nv_bfloat16 h = __float2bfloat16_rn(v);
    g_W1h[(size_t)n * Dd + k] = h;
    g_W1l[(size_t)n * Dd + k] = __float2bfloat16_rn(v - __bfloat162float(h));
}

// ---------------- CSR build ----------------
__global__ void zero_all_kernel() {   // zero all 4 CNT buffers at once
    int i = blockIdx.x * blockDim.x + threadIdx.x;
    if (i < Ss * Nn) ((int*)g_CNT)[i] = 0;
}

// 4 edges per thread via int4
__global__ void count_kernel(const int* __restrict__ dst, int buf) {
    int e4 = blockIdx.x * blockDim.x + threadIdx.x;
    if (e4 < Ee / 4) {
        int4 d = reinterpret_cast<const int4*>(dst)[e4];
        atomicAdd(&g_CNT[buf][d.x], 1);
        atomicAdd(&g_CNT[buf][d.y], 1);
        atomicAdd(&g_CNT[buf][d.z], 1);
        atomicAdd(&g_CNT[buf][d.w], 1);
    }
}

__global__ __launch_bounds__(1024) void scan1_kernel(int buf) {
    __shared__ int sh[1024];
    int i = blockIdx.x * 1024 + threadIdx.x;
    int v = (i < Nn) ? g_CNT[buf][i] : 0;
    sh[threadIdx.x] = v;
    __syncthreads();
    for (int off = 1; off < 1024; off <<= 1) {
        int t = 0;
        if (threadIdx.x >= off) t = sh[threadIdx.x - off];
        __syncthreads();
        sh[threadIdx.x] += t;
        __syncthreads();
    }
    if (i < Nn) g_ROWPTR[buf][i] = sh[threadIdx.x] - v;
    if (threadIdx.x == 1023) g_BSUM[buf][blockIdx.x] = sh[1023];
}

// parallel 128-wide Hillis-Steele over 98 block sums (exclusive)
__global__ __launch_bounds__(128) void scan2_kernel(int buf) {
    __shared__ int sh[128];
    int t = threadIdx.x;
    int v = (t < SCAN_BLOCKS) ? g_BSUM[buf][t] : 0;
    sh[t] = v;
    __syncthreads();
    for (int off = 1; off < 128; off <<= 1) {
        int x = 0;
        if (t >= off) x = sh[t - off];
        __syncthreads();
        sh[t] += x;
        __syncthreads();
    }
    if (t < SCAN_BLOCKS) g_BSUM[buf][t] = sh[t] - v;
}

__global__ void scan3_kernel(int buf) {
    int i = blockIdx.x * blockDim.x + threadIdx.x;
    if (i < Nn) {
        int r = g_ROWPTR[buf][i] + g_BSUM[buf][i >> 10];
        g_ROWPTR[buf][i] = r;
        g_CURS[buf][i]   = r;
        g_DINV[buf][i]   = rsqrtf((float)(g_CNT[buf][i] + 1));
    }
    if (i == 0) g_ROWPTR[buf][Nn] = Ee;
}

// 4 edges per thread via int4
__global__ void fill_kernel(const int* __restrict__ src,
                            const int* __restrict__ dst, int buf) {
    int e4 = blockIdx.x * blockDim.x + threadIdx.x;
    if (e4 < Ee / 4) {
        int4 s = reinterpret_cast<const int4*>(src)[e4];
        int4 d = reinterpret_cast<const int4*>(dst)[e4];
        int slot;
        slot = atomicAdd(&g_CURS[buf][d.x], 1); g_COL[buf][slot] = s.x;
        slot = atomicAdd(&g_CURS[buf][d.y], 1); g_COL[buf][slot] = s.y;
        slot = atomicAdd(&g_CURS[buf][d.z], 1); g_COL[buf][slot] = s.z;
        slot = atomicAdd(&g_CURS[buf][d.w], 1); g_COL[buf][slot] = s.w;
    }
}

// ---------------- pullX: AX[i] = sum_{j->i} X[j]*dinv_j*dinv_i + X[i]*d2 ---
__global__ __launch_bounds__(256) void pullX_kernel(const float* __restrict__ X,
                                                    int buf) {
    int warp = (blockIdx.x * blockDim.x + threadIdx.x) >> 5;
    int lane = threadIdx.x & 31;
    if (warp >= Nn) return;
    int i = warp;
    int beg = g_ROWPTR[buf][i], end = g_ROWPTR[buf][i + 1];
    const int*   COL  = g_COL[buf];
    const float* DINV = g_DINV[buf];
    const float4* X4 = reinterpret_cast<const float4*>(X);

    float di = DINV[i];
    float4 a = make_float4(0.f, 0.f, 0.f, 0.f);

    int e = beg;
    for (; e + 3 < end; e += 4) {
        int   s0 = COL[e],   s1 = COL[e + 1], s2 = COL[e + 2], s3 = COL[e + 3];
        float w0 = DINV[s0] * di, w1 = DINV[s1] * di;
        float w2 = DINV[s2] * di, w3 = DINV[s3] * di;
        float4 v0 = X4[(size_t)s0 * 32 + lane];
        float4 v1 = X4[(size_t)s1 * 32 + lane];
        float4 v2 = X4[(size_t)s2 * 32 + lane];
        float4 v3 = X4[(size_t)s3 * 32 + lane];
        fma4v(a, v0, w0); fma4v(a, v1, w1); fma4v(a, v2, w2); fma4v(a, v3, w3);
    }
    for (; e < end; e++) {
        int s0 = COL[e];
        fma4v(a, X4[(size_t)s0 * 32 + lane], DINV[s0] * di);
    }

    fma4v(a, X4[(size_t)i * 32 + lane], di * di);

    split_store4(g_AXh[buf], g_AXl[buf], (size_t)i * Dd + 4 * lane, a);
}

// ------------- gemm1 (tc, bf16x3): H1 = relu(AX @ W1 + b1), bf16-split out -
#define BMg 128
#define BNg 128
#define BKg 32
#define APAD 40

__device__ __forceinline__ void mma_bf16(
    float& d0, float& d1, float& d2, float& d3,
    unsigned a0, unsigned a1, unsigned a2, unsigned a3,
    unsigned b0, unsigned b1)
{
    asm volatile(
        "mma.sync.aligned.m16n8k16.row.col.f32.bf16.bf16.f32 "
        "{%0,%1,%2,%3}, {%4,%5,%6,%7}, {%8,%9}, {%0,%1,%2,%3};"
        : "+f"(d0), "+f"(d1), "+f"(d2), "+f"(d3)
        : "r"(a0), "r"(a1), "r"(a2), "r"(a3), "r"(b0), "r"(b1));
}

__global__ __launch_bounds__(256) void gemm1_kernel(const float* __restrict__ b1,
                                                    int buf)
{
    const int K = Dd;   // 128
    const int M = Nn;
    __shared__ __nv_bfloat16 Ah[BMg][APAD];
    __shared__ __nv_bfloat16 Al[BMg][APAD];
    __shared__ __nv_bfloat16 Bh[BNg][APAD];
    __shared__ __nv_bfloat16 Bl[BNg][APAD];

    const __nv_bfloat16* Ah_t = g_AXh[buf];
    const __nv_bfloat16* Al_t = g_AXl[buf];
    __nv_bfloat16* Ch = g_H1h[buf];
    __nv_bfloat16* Cl = g_H1l[buf];

    int tid = threadIdx.x;
    int wid = tid >> 5;
    int lane = tid & 31;
    int warp_m = wid >> 1;
    int warp_n = wid & 1;
    int g = lane >> 2;
    int c0 = (lane & 3) * 2;

    int rowBase = blockIdx.x * BMg;
    int colBase = blockIdx.y * BNg;

    float d[2][8][4];
#pragma unroll
    for (int im = 0; im < 2; im++)
#pragma unroll
        for (int jn = 0; jn < 8; jn++)
#pragma unroll
            for (int c = 0; c < 4; c++) d[im][jn][c] = 0.f;

    const uint4 z4 = make_uint4(0, 0, 0, 0);

    for (int k0 = 0; k0 < K; k0 += BKg) {
#pragma unroll
        for (int l = 0; l < 2; l++) {
            int f = tid + l * 256;
            int r = f >> 2;
            int kc = (f & 3) * 8;
            int gr = rowBase + r;
            uint4 va = z4, vl = z4;
            if (gr < M) {
                va = *reinterpret_cast<const uint4*>(&Ah_t[(size_t)gr * K + k0 + kc]);
                vl = *reinterpret_cast<const uint4*>(&Al_t[(size_t)gr * K + k0 + kc]);
            }
            *reinterpret_cast<uint4*>(&Ah[r][kc]) = va;
            *reinterpret_cast<uint4*>(&Al[r][kc]) = vl;
            int bn = colBase + r;
            uint4 vb  = *reinterpret_cast<const uint4*>(&g_W1h[(size_t)bn * K + k0 + kc]);
            uint4 vbl = *reinterpret_cast<const uint4*>(&g_W1l[(size_t)bn * K + k0 + kc]);
            *reinterpret_cast<uint4*>(&Bh[r][kc]) = vb;
            *reinterpret_cast<uint4*>(&Bl[r][kc]) = vbl;
        }
        __syncthreads();

#pragma unroll
        for (int kf = 0; kf < BKg; kf += 16) {
            unsigned ah[2][4], al[2][4];
#pragma unroll
            for (int im = 0; im < 2; im++) {
                int br = warp_m * 32 + im * 16 + g;
                ah[im][0] = *reinterpret_cast<const unsigned*>(&Ah[br][kf + c0]);
                ah[im][1] = *reinterpret_cast<const unsigned*>(&Ah[br + 8][kf + c0]);
                ah[im][2] = *reinterpret_cast<const unsigned*>(&Ah[br][kf + c0 + 8]);
                ah[im][3] = *reinterpret_cast<const unsigned*>(&Ah[br + 8][kf + c0 + 8]);
                al[im][0] = *reinterpret_cast<const unsigned*>(&Al[br][kf + c0]);
                al[im][1] = *reinterpret_cast<const unsigned*>(&Al[br + 8][kf + c0]);
                al[im][2] = *reinterpret_cast<const unsigned*>(&Al[br][kf + c0 + 8]);
                al[im][3] = *reinterpret_cast<const unsigned*>(&Al[br + 8][kf + c0 + 8]);
            }
#pragma unroll
            for (int jn = 0; jn < 8; jn++) {
                int bn = warp_n * 64 + jn * 8 + g;
                unsigned bh0 = *reinterpret_cast<const unsigned*>(&Bh[bn][kf + c0]);
                unsigned bh1 = *reinterpret_cast<const unsigned*>(&Bh[bn][kf + c0 + 8]);
                unsigned bl0 = *reinterpret_cast<const unsigned*>(&Bl[bn][kf + c0]);
                unsigned bl1 = *reinterpret_cast<const unsigned*>(&Bl[bn][kf + c0 + 8]);
#pragma unroll
                for (int im = 0; im < 2; im++) {
                    mma_bf16(d[im][jn][0], d[im][jn][1], d[im][jn][2], d[im][jn][3],
                             ah[im][0], ah[im][1], ah[im][2], ah[im][3], bh0, bh1);
                    mma_bf16(d[im][jn][0], d[im][jn][1], d[im][jn][2], d[im][jn][3],
                             ah[im][0], ah[im][1], ah[im][2], ah[im][3], bl0, bl1);
                    mma_bf16(d[im][jn][0], d[im][jn][1], d[im][jn][2], d[im][jn][3],
                             al[im][0], al[im][1], al[im][2], al[im][3], bh0, bh1);
                }
            }
        }
        __syncthreads();
    }

    // epilogue: +b1, relu, bf16 hi/lo split store
#pragma unroll
    for (int im = 0; im < 2; im++) {
        int r0 = rowBase + warp_m * 32 + im * 16 + g;
#pragma unroll
        for (int jn = 0; jn < 8; jn++) {
            int col = colBase + warp_n * 64 + jn * 8 + c0;
            float bb0 = __ldg(&b1[col]), bb1 = __ldg(&b1[col + 1]);
            if (r0 < M) {
                split_store2(Ch, Cl, (size_t)r0 * Hh + col,
                             fmaxf(d[im][jn][0] + bb0, 0.f),
                             fmaxf(d[im][jn][1] + bb1, 0.f));
            }
            if (r0 + 8 < M) {
                split_store2(Ch, Cl, (size_t)(r0 + 8) * Hh + col,
                             fmaxf(d[im][jn][2] + bb0, 0.f),
                             fmaxf(d[im][jn][3] + bb1, 0.f));
            }
        }
    }
}

// ---------------- pullH: AGG2[p] = Agg(H1)[post_idx[p]] --------------------
__global__ __launch_bounds__(256) void pullH_kernel(const int* __restrict__ post_idx,
                                                    int buf) {
    int warp = (blockIdx.x * blockDim.x + threadIdx.x) >> 5;
    int lane = threadIdx.x & 31;
    if (warp >= Pp) return;
    int p = warp;
    int i = post_idx[p];
    int beg = g_ROWPTR[buf][i], end = g_ROWPTR[buf][i + 1];
    const int*   COL  = g_COL[buf];
    const float* DINV = g_DINV[buf];
    const __nv_bfloat16* Hh_t = g_H1h[buf];
    const __nv_bfloat16* Hl_t = g_H1l[buf];

    float di = DINV[i];
    float4 a0 = make_float4(0.f, 0.f, 0.f, 0.f);
    float4 a1 = make_float4(0.f, 0.f, 0.f, 0.f);

    int e = beg;
    for (; e + 1 < end; e += 2) {
        int   s0 = COL[e],   s1 = COL[e + 1];
        float w0 = DINV[s0] * di, w1 = DINV[s1] * di;
        float4 v00 = load_split4(Hh_t, Hl_t, (size_t)s0 * Hh + 4 * lane);
        float4 v01 = load_split4(Hh_t, Hl_t, (size_t)s0 * Hh + 128 + 4 * lane);
        float4 v10 = load_split4(Hh_t, Hl_t, (size_t)s1 * Hh + 4 * lane);
        float4 v11 = load_split4(Hh_t, Hl_t, (size_t)s1 * Hh + 128 + 4 * lane);
        fma4v(a0, v00, w0); fma4v(a1, v01, w0);
        fma4v(a0, v10, w1); fma4v(a1, v11, w1);
    }
    if (e < end) {
        int s0 = COL[e];
        float w0 = DINV[s0] * di;
        fma4v(a0, load_split4(Hh_t, Hl_t, (size_t)s0 * Hh + 4 * lane), w0);
        fma4v(a1, load_split4(Hh_t, Hl_t, (size_t)s0 * Hh + 128 + 4 * lane), w0);
    }

    float d2 = di * di;
    fma4v(a0, load_split4(Hh_t, Hl_t, (size_t)i * Hh + 4 * lane), d2);
    fma4v(a1, load_split4(Hh_t, Hl_t, (size_t)i * Hh + 128 + 4 * lane), d2);

    float4* AG = reinterpret_cast<float4*>(g_AGG2[buf]);
    AG[(size_t)p * 64 + lane]      = a0;
    AG[(size_t)p * 64 + 32 + lane] = a1;
}

// ------- gemm2 (FFMA, ONCE): ACC = (0.25*ΣAGG2)@W2 + b2 + 0.25*ΣH1[post] ---
__global__ __launch_bounds__(256) void gemm2_kernel(
    const float* __restrict__ W2, const float* __restrict__ b2,
    const int* __restrict__ post_idx)
{
    const int BM = 128, BN = 128, BK = 16;
    const int M = Pp, K = Hh, Ncol = Hh;
    __shared__ float As[BK][BM];
    __shared__ float Bs[BK][BN];

    int tid = threadIdx.x;
    int rowBase = blockIdx.x * BM;
    int colBase = blockIdx.y * BN;
    int tr = tid >> 4;
    int tc = tid & 15;

    float acc[8][8];
#pragma unroll
    for (int i = 0; i < 8; i++)
#pragma unroll
        for (int j = 0; j < 8; j++) acc[i][j] = 0.f;

    for (int k0 = 0; k0 < K; k0 += BK) {
#pragma unroll
        for (int l = 0; l < 2; l++) {
            int f = tid + l * 256;
            int r = f >> 2;
            int cc = (f & 3) * 4;
            float4 v = make_float4(0.f, 0.f, 0.f, 0.f);
            int gr = rowBase + r;
            if (gr < M) {
                size_t off = (size_t)gr * K + k0 + cc;
                float4 v0 = *reinterpret_cast<const float4*>(&g_AGG2[0][off]);
                float4 v1 = *reinterpret_cast<const float4*>(&g_AGG2[1][off]);
                float4 v2 = *reinterpret_cast<const float4*>(&g_AGG2[2][off]);
                float4 v3 = *reinterpret_cast<const float4*>(&g_AGG2[3][off]);
                v.x = (v0.x + v1.x + v2.x + v3.x) * 0.25f;
                v.y = (v0.y + v1.y + v2.y + v3.y) * 0.25f;
                v.z = (v0.z + v1.z + v2.z + v3.z) * 0.25f;
                v.w = (v0.w + v1.w + v2.w + v3.w) * 0.25f;
            }
            As[cc + 0][r] = v.x; As[cc + 1][r] = v.y;
            As[cc + 2][r] = v.z; As[cc + 3][r] = v.w;
        }
#pragma unroll
        for (int l = 0; l < 2; l++) {
            int f = tid + l * 256;
            int r = f >> 5;
            int cc = (f & 31) * 4;
            float4 v = *reinterpret_cast<const float4*>(
                &W2[(size_t)(k0 + r) * Ncol + colBase + cc]);
            *reinterpret_cast<float4*>(&Bs[r][cc]) = v;
        }
        __syncthreads();

#pragma unroll
        for (int k = 0; k < BK; k++) {
            float ra[8], rb[8];
#pragma unroll
            for (int i = 0; i < 8; i++) ra[i] = As[k][tr * 8 + i];
#pragma unroll
            for (int j = 0; j < 8; j++) rb[j] = Bs[k][tc * 8 + j];
#pragma unroll
            for (int i = 0; i < 8; i++)
#pragma unroll
                for (int j = 0; j < 8; j++)
                    acc[i][j] = fmaf(ra[i], rb[j], acc[i][j]);
        }
        __syncthreads();
    }

#pragma unroll
    for (int i = 0; i < 8; i++) {
        int gr = rowBase + tr * 8 + i;
        if (gr < M) {
            int node = post_idx[gr];
#pragma unroll
            for (int j = 0; j < 8; j += 4) {
                int col = colBase + tc * 8 + j;
                float4 bb = *reinterpret_cast<const float4*>(&b2[col]);
                size_t hoff = (size_t)node * Hh + col;
                float4 h0 = load_split4(g_H1h[0], g_H1l[0], hoff);
                float4 h1 = load_split4(g_H1h[1], g_H1l[1], hoff);
                float4 h2 = load_split4(g_H1h[2], g_H1l[2], hoff);
                float4 h3 = load_split4(g_H1h[3], g_H1l[3], hoff);
                float4 v;
                v.x = acc[i][j]     + bb.x + (h0.x + h1.x + h2.x + h3.x) * 0.25f;
                v.y = acc[i][j + 1] + bb.y + (h0.y + h1.y + h2.y + h3.y) * 0.25f;
                v.z = acc[i][j + 2] + bb.z + (h0.z + h1.z + h2.z + h3.z) * 0.25f;
                v.w = acc[i][j + 3] + bb.w + (h0.w + h1.w + h2.w + h3.w) * 0.25f;
                *reinterpret_cast<float4*>(&g_ACC[(size_t)gr * Hh + col]) = v;
            }
        }
    }
}

// ---------------- classifier ----------------
__global__ __launch_bounds__(128) void classifier_kernel(
    const float* __restrict__ Wc1, const float* __restrict__ bc1,
    const float* __restrict__ Wc2, const float* __restrict__ bc2,
    float* __restrict__ out)
{
    __shared__ float post[Hh];
    __shared__ float red[128];
    int p = blockIdx.x;
    int t = threadIdx.x;
    post[t]       = g_ACC[(size_t)p * Hh + t];
    post[t + 128] = g_ACC[(size_t)p * Hh + t + 128];
    __syncthreads();

    float acc = bc1[t];
#pragma unroll 8
    for (int j = 0; j < Hh; j++)
        acc = fmaf(post[j], Wc1[(size_t)j * 128 + t], acc);
    acc = fmaxf(acc, 0.f);
    float v = acc * Wc2[t];

    red[t] = v;
    __syncthreads();
    for (int off = 64; off > 0; off >>= 1) {
        if (t < off) red[t] += red[t + off];
        __syncthreads();
    }
    if (t == 0) {
        float lg = red[0] + bc2[0];
        out[p] = 1.f / (1.f + expf(-lg));
    }
}

// -------- launch: main builds CSR(2,3) while workers run chains ------------
static cudaStream_t s_sA = nullptr, s_sB = nullptr;
static cudaEvent_t  s_evW, s_evA, s_evB, s_evC2, s_evC3;

static void build_csr(const int* EI, int s, cudaStream_t st) {
    const int nblk_node = (Nn + 255) / 256;
    const int nblk_edge4 = (Ee / 4 + 255) / 256;   // 1563
    const int* src = EI + (size_t)s * 2 * Ee;
    const int* dst = src + Ee;
    count_kernel<<<nblk_edge4, 256, 0, st>>>(dst, s);
    scan1_kernel<<<SCAN_BLOCKS, 1024, 0, st>>>(s);
    scan2_kernel<<<1, 128, 0, st>>>(s);
    scan3_kernel<<<nblk_node, 256, 0, st>>>(s);
    fill_kernel<<<nblk_edge4, 256, 0, st>>>(src, dst, s);
}

static void run_compute(const float* X, const float* b1, const int* post_idx,
                        int s, cudaStream_t st) {
    const int nblk_px = (Nn + 7) / 8;
    const int nblk_ph = (Pp + 7) / 8;
    dim3 g1_grid((Nn + BMg - 1) / BMg, Hh / BNg);
    pullX_kernel<<<nblk_px, 256, 0, st>>>(X, s);
    gemm1_kernel<<<g1_grid, 256, 0, st>>>(b1, s);
    pullH_kernel<<<nblk_ph, 256, 0, st>>>(post_idx, s);
}

extern "C" void kernel_launch(void* const* d_in, const int* in_sizes, int n_in,
                              void* d_out, int out_size)
{
    const float* X        = (const float*)d_in[0];
    const int*   EI       = (const int*)  d_in[1];
    const int*   post_idx = (const int*)  d_in[2];
    const float* W1       = (const float*)d_in[3];
    const float* b1       = (const float*)d_in[4];
    const float* W2       = (const float*)d_in[5];
    const float* b2       = (const float*)d_in[6];
    const float* Wc1      = (const float*)d_in[7];
    const float* bc1      = (const float*)d_in[8];
    const float* Wc2      = (const float*)d_in[9];
    const float* bc2      = (const float*)d_in[10];
    float* out = (float*)d_out;

    if (!s_sA) {
        cudaStreamCreateWithFlags(&s_sA, cudaStreamNonBlocking);
        cudaStreamCreateWithFlags(&s_sB, cudaStreamNonBlocking);
        cudaEventCreateWithFlags(&s_evW, cudaEventDisableTiming);
        cudaEventCreateWithFlags(&s_evA, cudaEventDisableTiming);
        cudaEventCreateWithFlags(&s_evB, cudaEventDisableTiming);
        cudaEventCreateWithFlags(&s_evC2, cudaEventDisableTiming);
        cudaEventCreateWithFlags(&s_evC3, cudaEventDisableTiming);
    }

    // main: zero all CNT buffers + one-time W1 split, then fork
    zero_all_kernel<<<(Ss * Nn + 255) / 256, 256>>>();
    split_w1_kernel<<<(Dd * Hh + 255) / 256, 256>>>(W1);
    cudaEventRecord(s_evW, 0);
    cudaStreamWaitEvent(s_sA, s_evW, 0);
    cudaStreamWaitEvent(s_sB, s_evW, 0);

    // main (now idle until join): build CSR(2) and CSR(3) concurrently
    build_csr(EI, 2, 0);
    cudaEventRecord(s_evC2, 0);
    build_csr(EI, 3, 0);
    cudaEventRecord(s_evC3, 0);

    // stream A: CSR(0) + chain 0, then chain 2 (CSR from main)
    build_csr(EI, 0, s_sA);
    run_compute(X, b1, post_idx, 0, s_sA);
    cudaStreamWaitEvent(s_sA, s_evC2, 0);
    run_compute(X, b1, post_idx, 2, s_sA);
    cudaEventRecord(s_evA, s_sA);

    // stream B: CSR(1) + chain 1, then chain 3 (CSR from main)
    build_csr(EI, 1, s_sB);
    run_compute(X, b1, post_idx, 1, s_sB);
    cudaStreamWaitEvent(s_sB, s_evC3, 0);
    run_compute(X, b1, post_idx, 3, s_sB);
    cudaEventRecord(s_evB, s_sB);

    // join: single gemm2 over the snapshot mean, then classify
    cudaStreamWaitEvent(0, s_evA, 0);
    cudaStreamWaitEvent(0, s_evB, 0);
    dim3 g2_grid((Pp + 127) / 128, Hh / 128);
    gemm2_kernel<<<g2_grid, 256>>>(W2, b2, post_idx);
    classifier_kernel<<<Pp, 128>>>(Wc1, bc1, Wc2, bc2, out);
}